// round 4
// baseline (speedup 1.0000x reference)
#include <cuda_runtime.h>

// Problem constants
#define CCH     12            // path channels: 1 time + 3 orig + 8 aug
#define TT      1024
#define NSTEP   1023
#define NCHUNK  31
#define CHLEN   33            // 31 * 33 = 1023
#define NPATH   64            // B(32) * GROUPS(2)
#define SIGC    1884          // 12 + 144 + 1728
#define L2OFF   12
#define L3OFF   156
#define TSTRIDE 36            // padded t-stride of transposed dx (16B aligned)
#define SIGQ    471           // SIGC / 4 float4s

// Scratch (no cudaMalloc allowed)
__device__ __align__(16) float g_part[NPATH * NCHUNK * SIGC]; // ~15 MB

// ---------------------------------------------------------------------------
// Kernel 1: per-chunk partial signature.
// grid = (NCHUNK, NPATH), block = 160 (144 active compute threads).
// Thread (i,j) owns S3[i][j][0..11] + S2[i][j] + private S1[i].
// dx kept in TWO layouts: [t][c] (broadcast float4 k-loads) and transposed
// [c][t] (di/dj for 4 consecutive steps from ONE LDS.128).
// ---------------------------------------------------------------------------
__global__ __launch_bounds__(160) void chunk_kernel(const float* __restrict__ x,
                                                    const float* __restrict__ aug_w)
{
    __shared__ __align__(16) float dxsh[CHLEN * CCH];       // [t][c]
    __shared__ __align__(16) float dxT [CCH * TSTRIDE];     // [c][t_padded]
    __shared__ float xsh[(CHLEN + 1) * 3];
    __shared__ float awsh[8 * 3];

    const int tid   = threadIdx.x;
    const int chunk = blockIdx.x;
    const int p     = blockIdx.y;        // path id = b*2 + g
    const int b     = p >> 1;
    const int g     = p & 1;
    const int t0    = chunk * CHLEN;

    for (int idx = tid; idx < (CHLEN + 1) * 3; idx += blockDim.x)
        xsh[idx] = x[(b * TT + t0) * 3 + idx];
    if (tid < 24) awsh[tid] = aug_w[g * 24 + tid];
    __syncthreads();

    for (int idx = tid; idx < CHLEN * CCH; idx += blockDim.x) {
        int t = idx / CCH, c = idx - t * CCH;
        float xd0 = xsh[(t + 1) * 3 + 0] - xsh[t * 3 + 0];
        float xd1 = xsh[(t + 1) * 3 + 1] - xsh[t * 3 + 1];
        float xd2 = xsh[(t + 1) * 3 + 2] - xsh[t * 3 + 2];
        float v;
        if (c == 0)      v = 1.0f / 1023.0f;
        else if (c == 1) v = xd0;
        else if (c == 2) v = xd1;
        else if (c == 3) v = xd2;
        else {
            int e = c - 4;
            v = fmaf(awsh[e * 3 + 0], xd0,
                fmaf(awsh[e * 3 + 1], xd1,
                     awsh[e * 3 + 2] * xd2));
        }
        dxsh[idx] = v;
        dxT[c * TSTRIDE + t] = v;
    }
    __syncthreads();

    if (tid < 144) {
        const int i = tid / CCH, j = tid - CCH * (tid / CCH);
        float S3[12];
#pragma unroll
        for (int k = 0; k < 12; k++) S3[k] = 0.0f;
        float S2 = 0.0f;
        float s1 = 0.0f;
        const float4* __restrict__ dxq = (const float4*)dxsh;
        const float4* __restrict__ diT = (const float4*)(dxT + i * TSTRIDE);
        const float4* __restrict__ djT = (const float4*)(dxT + j * TSTRIDE);

#define SIG_STEP(tq, di_, dj_) {                                              \
        const float4 d0 = dxq[(tq) * 3 + 0];                                  \
        const float4 d1 = dxq[(tq) * 3 + 1];                                  \
        const float4 d2 = dxq[(tq) * 3 + 2];                                  \
        const float cc = fmaf(fmaf((di_), 1.0f/6.0f, 0.5f * s1), (dj_), S2);  \
        S3[0]  = fmaf(cc, d0.x, S3[0]);                                       \
        S3[1]  = fmaf(cc, d0.y, S3[1]);                                       \
        S3[2]  = fmaf(cc, d0.z, S3[2]);                                       \
        S3[3]  = fmaf(cc, d0.w, S3[3]);                                       \
        S3[4]  = fmaf(cc, d1.x, S3[4]);                                       \
        S3[5]  = fmaf(cc, d1.y, S3[5]);                                       \
        S3[6]  = fmaf(cc, d1.z, S3[6]);                                       \
        S3[7]  = fmaf(cc, d1.w, S3[7]);                                       \
        S3[8]  = fmaf(cc, d2.x, S3[8]);                                       \
        S3[9]  = fmaf(cc, d2.y, S3[9]);                                       \
        S3[10] = fmaf(cc, d2.z, S3[10]);                                      \
        S3[11] = fmaf(cc, d2.w, S3[11]);                                      \
        S2 = fmaf(fmaf((di_), 0.5f, s1), (dj_), S2);                          \
        s1 += (di_); }

#pragma unroll 4
        for (int tb = 0; tb < 8; tb++) {
            const float4 di4 = diT[tb];
            const float4 dj4 = djT[tb];
            SIG_STEP(tb * 4 + 0, di4.x, dj4.x);
            SIG_STEP(tb * 4 + 1, di4.y, dj4.y);
            SIG_STEP(tb * 4 + 2, di4.z, dj4.z);
            SIG_STEP(tb * 4 + 3, di4.w, dj4.w);
        }
        {   // remainder step t = 32
            const float di = dxT[i * TSTRIDE + 32];
            const float dj = dxT[j * TSTRIDE + 32];
            SIG_STEP(32, di, dj);
        }
#undef SIG_STEP

        float* out = &g_part[(size_t)(p * NCHUNK + chunk) * SIGC];
        if (j == 0) out[i] = s1;
        out[L2OFF + tid] = S2;
        float4* o4 = (float4*)(out + L3OFF + tid * 12);
        o4[0] = make_float4(S3[0], S3[1], S3[2],  S3[3]);
        o4[1] = make_float4(S3[4], S3[5], S3[6],  S3[7]);
        o4[2] = make_float4(S3[8], S3[9], S3[10], S3[11]);
    }
}

// ---------------------------------------------------------------------------
// Kernel 2 (fused): per-batch combine (both groups) + GEMV + sigmoid.
// grid = 32 (batch), block = 1024.
// Fold loop is a double-buffered smem pipeline: 942 threads stage the next
// chunk partial (both groups, coalesced float4 LDG), 864 threads fold the
// current chunk from shared. One __syncthreads per fold.
// ---------------------------------------------------------------------------
__global__ __launch_bounds__(1024) void combine_linear_kernel(
        const float* __restrict__ lin_w,
        const float* __restrict__ lin_b,
        float* __restrict__ out)
{
    __shared__ __align__(16) float sig[2 * SIGC];       // 15 KB result
    __shared__ __align__(16) float buf[2][2 * SIGC];    // double buffer, 30 KB

    const int tid = threadIdx.x;
    const int b   = blockIdx.x;

    // Staging roles: tid < 942 stages one float4 per fold.
    const int sgrp = (tid < 942) ? (tid / SIGQ) : 0;    // group 0/1
    const int sidx = (tid < 942) ? (tid - SIGQ * sgrp) : 0;
    const float4* __restrict__ src =
        (const float4*)&g_part[(size_t)(2 * b + sgrp) * NCHUNK * SIGC] + sidx;

    // Compute roles: tid < 864 folds; thread = (grp, i, j, kg)
    const int grp  = tid / 432;
    const int u    = tid - 432 * grp;
    const int t144 = u / 3;
    const int kg   = u - 3 * t144;
    const int i    = t144 / CCH;
    const int j    = t144 - CCH * i;

#define STAGE(ch, par) \
    if (tid < 942) ((float4*)&buf[par][sgrp * SIGC])[sidx] = src[(size_t)(ch) * (SIGC/4)];

    // Stage chunk 0, init accumulators from it.
    STAGE(0, 0);
    __syncthreads();

    float4 A3 = make_float4(0.f, 0.f, 0.f, 0.f);
    float  A2ij = 0.f, a1i = 0.f;
    if (tid < 864) {
        const float* bp0 = &buf[0][grp * SIGC];
        A3   = *(const float4*)(bp0 + L3OFF + t144 * 12 + kg * 4);
        A2ij = bp0[L2OFF + t144];
        a1i  = bp0[i];
    }
    STAGE(1, 1);
    __syncthreads();   // init reads of buf0 done; buf1 staged

    for (int ch = 1; ch < NCHUNK; ch++) {
        if (ch + 1 < NCHUNK) { STAGE(ch + 1, (ch + 1) & 1); }
        if (tid < 864) {
            const float* __restrict__ bp = &buf[ch & 1][grp * SIGC];
            const float4 u4  = *(const float4*)(bp + kg * 4);                     // B1 quad
            const float  b1i = bp[i];
            const float  b1j = bp[j];
            const float4 q   = *(const float4*)(bp + L2OFF + j * 12 + kg * 4);    // B2[j] quad
            const float  b2  = bp[L2OFF + i * CCH + j];
            const float4 r   = *(const float4*)(bp + L3OFF + t144 * 12 + kg * 4); // B3 quad

            // old A1, old A2
            A3.x += r.x; A3.x = fmaf(a1i, q.x, A3.x); A3.x = fmaf(A2ij, u4.x, A3.x);
            A3.y += r.y; A3.y = fmaf(a1i, q.y, A3.y); A3.y = fmaf(A2ij, u4.y, A3.y);
            A3.z += r.z; A3.z = fmaf(a1i, q.z, A3.z); A3.z = fmaf(A2ij, u4.z, A3.z);
            A3.w += r.w; A3.w = fmaf(a1i, q.w, A3.w); A3.w = fmaf(A2ij, u4.w, A3.w);
            A2ij += b2 + a1i * b1j;   // old A1
            a1i  += b1i;
        }
        __syncthreads();
    }
#undef STAGE

    if (tid < 864) {
        float* so = &sig[grp * SIGC];
        *(float4*)(so + L3OFF + t144 * 12 + kg * 4) = A3;
        if (kg == 0) {
            so[L2OFF + t144] = A2ij;
            if (j == 0) so[i] = a1i;
        }
    }
    __syncthreads();

    // Phase B: GEMV + sigmoid. Warp o handles output o.
    const int o    = tid >> 5;
    const int lane = tid & 31;
    const float4* __restrict__ s4 = (const float4*)sig;
    const float4* __restrict__ w4 = (const float4*)(lin_w + (size_t)o * 2 * SIGC);
    const int NV = (2 * SIGC) / 4;   // 942

    float ax = 0.0f, ay = 0.0f, az = 0.0f, aw = 0.0f;
    for (int f = lane; f < NV; f += 32) {
        float4 sv = s4[f];
        float4 wv = w4[f];
        ax = fmaf(sv.x, wv.x, ax);
        ay = fmaf(sv.y, wv.y, ay);
        az = fmaf(sv.z, wv.z, az);
        aw = fmaf(sv.w, wv.w, aw);
    }
    float acc = (ax + ay) + (az + aw);
#pragma unroll
    for (int off = 16; off > 0; off >>= 1)
        acc += __shfl_down_sync(0xffffffffu, acc, off);
    if (lane == 0) {
        float z = acc + lin_b[o];
        out[b * 32 + o] = 1.0f / (1.0f + expf(-z));
    }
}

// ---------------------------------------------------------------------------
extern "C" void kernel_launch(void* const* d_in, const int* in_sizes, int n_in,
                              void* d_out, int out_size)
{
    const float* x     = (const float*)d_in[0];  // (32,1024,3)
    const float* aug_w = (const float*)d_in[1];  // (2,8,3)
    // d_in[2] = aug_b : unused (signature is translation-invariant)
    const float* lin_w = (const float*)d_in[3];  // (32, 3768)
    const float* lin_b = (const float*)d_in[4];  // (32,)
    float* out = (float*)d_out;                  // (32,32) float32

    dim3 grid1(NCHUNK, NPATH);
    chunk_kernel<<<grid1, 160>>>(x, aug_w);
    combine_linear_kernel<<<32, 1024>>>(lin_w, lin_b, out);
}

// round 5
// speedup vs baseline: 1.2176x; 1.2176x over previous
#include <cuda_runtime.h>

// Problem constants
#define CCH     12            // path channels: 1 time + 3 orig + 8 aug
#define TT      1024
#define NCHUNK  31
#define CHLEN   33            // 31 * 33 = 1023
#define NPATH   64            // B(32) * GROUPS(2)
#define SIGC    1884          // 12 + 144 + 1728
#define L2OFF   12
#define L3OFF   156
#define TSTRIDE 36            // padded t-stride of transposed dx
#define SIGQ    471           // SIGC / 4 float4s
#define NSEG    8             // level-1 segments per path (ceil(31/4))

// Scratch (no cudaMalloc allowed)
__device__ __align__(16) float g_part [NPATH * NCHUNK * SIGC]; // ~15 MB
__device__ __align__(16) float g_part2[NPATH * NSEG   * SIGC]; // ~3.9 MB

// ---------------------------------------------------------------------------
// Chen fold body: A = A (x) B (truncated, depth 3), thread owns (i,j,kg).
// ---------------------------------------------------------------------------
__device__ __forceinline__ void chen_fold(const float* __restrict__ bp,
        int i, int j, int t144, int kg,
        float4& A3, float& A2ij, float& a1i)
{
    const float4 u4  = *(const float4*)(bp + kg * 4);                     // B1 quad
    const float  b1i = bp[i];
    const float  b1j = bp[j];
    const float4 q   = *(const float4*)(bp + L2OFF + j * 12 + kg * 4);    // B2[j] quad
    const float  b2  = bp[L2OFF + i * CCH + j];
    const float4 r   = *(const float4*)(bp + L3OFF + t144 * 12 + kg * 4); // B3 quad

    // old A1, old A2
    A3.x += r.x; A3.x = fmaf(a1i, q.x, A3.x); A3.x = fmaf(A2ij, u4.x, A3.x);
    A3.y += r.y; A3.y = fmaf(a1i, q.y, A3.y); A3.y = fmaf(A2ij, u4.y, A3.y);
    A3.z += r.z; A3.z = fmaf(a1i, q.z, A3.z); A3.z = fmaf(A2ij, u4.z, A3.z);
    A3.w += r.w; A3.w = fmaf(a1i, q.w, A3.w); A3.w = fmaf(A2ij, u4.w, A3.w);
    A2ij += b2 + a1i * b1j;   // old A1
    a1i  += b1i;
}

// ---------------------------------------------------------------------------
// Kernel 1: per-chunk partial signature (unchanged from R3 winner).
// grid = (NCHUNK, NPATH), block = 160 (144 active).
// ---------------------------------------------------------------------------
__global__ __launch_bounds__(160) void chunk_kernel(const float* __restrict__ x,
                                                    const float* __restrict__ aug_w)
{
    __shared__ __align__(16) float dxsh[CHLEN * CCH];       // [t][c]
    __shared__ __align__(16) float dxT [CCH * TSTRIDE];     // [c][t_padded]
    __shared__ float xsh[(CHLEN + 1) * 3];
    __shared__ float awsh[8 * 3];

    const int tid   = threadIdx.x;
    const int chunk = blockIdx.x;
    const int p     = blockIdx.y;        // path id = b*2 + g
    const int b     = p >> 1;
    const int g     = p & 1;
    const int t0    = chunk * CHLEN;

    for (int idx = tid; idx < (CHLEN + 1) * 3; idx += blockDim.x)
        xsh[idx] = x[(b * TT + t0) * 3 + idx];
    if (tid < 24) awsh[tid] = aug_w[g * 24 + tid];
    __syncthreads();

    for (int idx = tid; idx < CHLEN * CCH; idx += blockDim.x) {
        int t = idx / CCH, c = idx - t * CCH;
        float xd0 = xsh[(t + 1) * 3 + 0] - xsh[t * 3 + 0];
        float xd1 = xsh[(t + 1) * 3 + 1] - xsh[t * 3 + 1];
        float xd2 = xsh[(t + 1) * 3 + 2] - xsh[t * 3 + 2];
        float v;
        if (c == 0)      v = 1.0f / 1023.0f;
        else if (c == 1) v = xd0;
        else if (c == 2) v = xd1;
        else if (c == 3) v = xd2;
        else {
            int e = c - 4;
            v = fmaf(awsh[e * 3 + 0], xd0,
                fmaf(awsh[e * 3 + 1], xd1,
                     awsh[e * 3 + 2] * xd2));
        }
        dxsh[idx] = v;
        dxT[c * TSTRIDE + t] = v;
    }
    __syncthreads();

    if (tid < 144) {
        const int i = tid / CCH, j = tid - CCH * (tid / CCH);
        float S3[12];
#pragma unroll
        for (int k = 0; k < 12; k++) S3[k] = 0.0f;
        float S2 = 0.0f;
        float s1 = 0.0f;
        const float4* __restrict__ dxq = (const float4*)dxsh;
        const float4* __restrict__ diT = (const float4*)(dxT + i * TSTRIDE);
        const float4* __restrict__ djT = (const float4*)(dxT + j * TSTRIDE);

#define SIG_STEP(tq, di_, dj_) {                                              \
        const float4 d0 = dxq[(tq) * 3 + 0];                                  \
        const float4 d1 = dxq[(tq) * 3 + 1];                                  \
        const float4 d2 = dxq[(tq) * 3 + 2];                                  \
        const float cc = fmaf(fmaf((di_), 1.0f/6.0f, 0.5f * s1), (dj_), S2);  \
        S3[0]  = fmaf(cc, d0.x, S3[0]);                                       \
        S3[1]  = fmaf(cc, d0.y, S3[1]);                                       \
        S3[2]  = fmaf(cc, d0.z, S3[2]);                                       \
        S3[3]  = fmaf(cc, d0.w, S3[3]);                                       \
        S3[4]  = fmaf(cc, d1.x, S3[4]);                                       \
        S3[5]  = fmaf(cc, d1.y, S3[5]);                                       \
        S3[6]  = fmaf(cc, d1.z, S3[6]);                                       \
        S3[7]  = fmaf(cc, d1.w, S3[7]);                                       \
        S3[8]  = fmaf(cc, d2.x, S3[8]);                                       \
        S3[9]  = fmaf(cc, d2.y, S3[9]);                                       \
        S3[10] = fmaf(cc, d2.z, S3[10]);                                      \
        S3[11] = fmaf(cc, d2.w, S3[11]);                                      \
        S2 = fmaf(fmaf((di_), 0.5f, s1), (dj_), S2);                          \
        s1 += (di_); }

#pragma unroll 4
        for (int tb = 0; tb < 8; tb++) {
            const float4 di4 = diT[tb];
            const float4 dj4 = djT[tb];
            SIG_STEP(tb * 4 + 0, di4.x, dj4.x);
            SIG_STEP(tb * 4 + 1, di4.y, dj4.y);
            SIG_STEP(tb * 4 + 2, di4.z, dj4.z);
            SIG_STEP(tb * 4 + 3, di4.w, dj4.w);
        }
        {   // remainder step t = 32
            const float di = dxT[i * TSTRIDE + 32];
            const float dj = dxT[j * TSTRIDE + 32];
            SIG_STEP(32, di, dj);
        }
#undef SIG_STEP

        float* out = &g_part[(size_t)(p * NCHUNK + chunk) * SIGC];
        if (j == 0) out[i] = s1;
        out[L2OFF + tid] = S2;
        float4* o4 = (float4*)(out + L3OFF + tid * 12);
        o4[0] = make_float4(S3[0], S3[1], S3[2],  S3[3]);
        o4[1] = make_float4(S3[4], S3[5], S3[6],  S3[7]);
        o4[2] = make_float4(S3[8], S3[9], S3[10], S3[11]);
    }
}

// ---------------------------------------------------------------------------
// Kernel 2 (tree level 1): fold groups of <=4 chunks into segment partials.
// grid = (NSEG, NPATH) = 512 blocks, block = 448 (432 active).
// Chunks bulk-staged to smem (coalesced), folds read from smem.
// ---------------------------------------------------------------------------
__global__ __launch_bounds__(448) void seg_combine_kernel()
{
    __shared__ __align__(16) float sbuf[4 * SIGC];   // up to 4 chunks, 30 KB

    const int tid = threadIdx.x;
    const int seg = blockIdx.x;
    const int p   = blockIdx.y;
    const int c0  = seg * 4;
    const int nch = (NCHUNK - c0 < 4) ? (NCHUNK - c0) : 4;   // 4 (or 3 for seg 7)

    const float4* __restrict__ gsrc =
        (const float4*)&g_part[((size_t)p * NCHUNK + c0) * SIGC];
    const int nq = nch * SIGQ;
    for (int f = tid; f < nq; f += 448)
        ((float4*)sbuf)[f] = gsrc[f];
    __syncthreads();

    if (tid < 432) {
        const int t144 = tid / 3;
        const int kg   = tid - 3 * t144;
        const int i    = t144 / CCH;
        const int j    = t144 - CCH * i;

        float4 A3   = *(const float4*)(sbuf + L3OFF + t144 * 12 + kg * 4);
        float  A2ij = sbuf[L2OFF + t144];
        float  a1i  = sbuf[i];

#pragma unroll
        for (int ch = 1; ch < 4; ch++) {
            if (ch >= nch) break;
            chen_fold(sbuf + ch * SIGC, i, j, t144, kg, A3, A2ij, a1i);
        }

        float* out = &g_part2[(size_t)(p * NSEG + seg) * SIGC];
        *(float4*)(out + L3OFF + t144 * 12 + kg * 4) = A3;
        if (kg == 0) {
            out[L2OFF + t144] = A2ij;
            if (j == 0) out[i] = a1i;
        }
    }
}

// ---------------------------------------------------------------------------
// Kernel 3 (tree level 2 + GEMV + sigmoid). grid = 32 (batch), block = 1024.
// Stage ALL 16 segment partials (2 groups x 8 segs = 120 KB) into dynamic
// smem in one coalesced burst, fold 7 times from smem, GEMV from smem.
// ---------------------------------------------------------------------------
extern __shared__ float dynbuf[];   // [2 * NSEG * SIGC] floats

__global__ __launch_bounds__(1024) void combine_linear_kernel(
        const float* __restrict__ lin_w,
        const float* __restrict__ lin_b,
        float* __restrict__ out)
{
    const int tid = threadIdx.x;
    const int b   = blockIdx.x;

    // Bulk stage: both groups' segment partials are contiguous in g_part2.
    const float4* __restrict__ gsrc =
        (const float4*)&g_part2[(size_t)(2 * b) * NSEG * SIGC];
    const int NQ = 2 * NSEG * SIGQ;   // 7536 float4s
    for (int f = tid; f < NQ; f += 1024)
        ((float4*)dynbuf)[f] = gsrc[f];
    __syncthreads();

    float4 A3 = make_float4(0.f, 0.f, 0.f, 0.f);
    float  A2ij = 0.f, a1i = 0.f;
    int grp = 0, i = 0, j = 0, t144 = 0, kg = 0;
    if (tid < 864) {
        grp  = tid / 432;
        const int u = tid - 432 * grp;
        t144 = u / 3;
        kg   = u - 3 * t144;
        i    = t144 / CCH;
        j    = t144 - CCH * i;

        const float* __restrict__ base = dynbuf + (size_t)grp * NSEG * SIGC;
        A3   = *(const float4*)(base + L3OFF + t144 * 12 + kg * 4);
        A2ij = base[L2OFF + t144];
        a1i  = base[i];
#pragma unroll
        for (int s = 1; s < NSEG; s++)
            chen_fold(base + s * SIGC, i, j, t144, kg, A3, A2ij, a1i);
    }
    __syncthreads();   // all seg-0 reads complete before overwrite

    if (tid < 864) {
        float* so = dynbuf + (size_t)grp * NSEG * SIGC;   // reuse seg-0 slot
        *(float4*)(so + L3OFF + t144 * 12 + kg * 4) = A3;
        if (kg == 0) {
            so[L2OFF + t144] = A2ij;
            if (j == 0) so[i] = a1i;
        }
    }
    __syncthreads();

    // GEMV + sigmoid: warp o -> out[b][o]. sig(group g) at dynbuf + g*NSEG*SIGC.
    const int o    = tid >> 5;
    const int lane = tid & 31;
    const float4* __restrict__ s0 = (const float4*)(dynbuf);
    const float4* __restrict__ s1 = (const float4*)(dynbuf + (size_t)NSEG * SIGC);
    const float4* __restrict__ w4 = (const float4*)(lin_w + (size_t)o * 2 * SIGC);

    float ax = 0.0f, ay = 0.0f, az = 0.0f, aw = 0.0f;
    for (int f = lane; f < SIGQ; f += 32) {
        float4 sv = s0[f];
        float4 wv = w4[f];
        ax = fmaf(sv.x, wv.x, ax);
        ay = fmaf(sv.y, wv.y, ay);
        az = fmaf(sv.z, wv.z, az);
        aw = fmaf(sv.w, wv.w, aw);
    }
    for (int f = lane; f < SIGQ; f += 32) {
        float4 sv = s1[f];
        float4 wv = w4[SIGQ + f];
        ax = fmaf(sv.x, wv.x, ax);
        ay = fmaf(sv.y, wv.y, ay);
        az = fmaf(sv.z, wv.z, az);
        aw = fmaf(sv.w, wv.w, aw);
    }
    float acc = (ax + ay) + (az + aw);
#pragma unroll
    for (int off = 16; off > 0; off >>= 1)
        acc += __shfl_down_sync(0xffffffffu, acc, off);
    if (lane == 0) {
        float z = acc + lin_b[o];
        out[b * 32 + o] = 1.0f / (1.0f + expf(-z));
    }
}

// ---------------------------------------------------------------------------
extern "C" void kernel_launch(void* const* d_in, const int* in_sizes, int n_in,
                              void* d_out, int out_size)
{
    const float* x     = (const float*)d_in[0];  // (32,1024,3)
    const float* aug_w = (const float*)d_in[1];  // (2,8,3)
    // d_in[2] = aug_b : unused (signature is translation-invariant)
    const float* lin_w = (const float*)d_in[3];  // (32, 3768)
    const float* lin_b = (const float*)d_in[4];  // (32,)
    float* out = (float*)d_out;                  // (32,32) float32

    const int dyn_smem = 2 * NSEG * SIGC * (int)sizeof(float);   // 120,576 B
    cudaFuncSetAttribute(combine_linear_kernel,
                         cudaFuncAttributeMaxDynamicSharedMemorySize, dyn_smem);

    dim3 grid1(NCHUNK, NPATH);
    chunk_kernel<<<grid1, 160>>>(x, aug_w);
    dim3 grid2(NSEG, NPATH);
    seg_combine_kernel<<<grid2, 448>>>();
    combine_linear_kernel<<<32, 1024, dyn_smem>>>(lin_w, lin_b, out);
}

// round 6
// speedup vs baseline: 1.3770x; 1.1309x over previous
#include <cuda_runtime.h>

// Problem constants
#define CCH     12            // path channels: 1 time + 3 orig + 8 aug
#define TT      1024
#define NCHUNK  16
#define CHLEN   64            // chunk 15 has 63 steps (16*64-1 = 1023)
#define NPATH   64            // B(32) * GROUPS(2)
#define SIGC    1884          // 12 + 144 + 1728
#define L2OFF   12
#define L3OFF   156
#define TSTRIDE 68            // padded t-stride of transposed dx (float4-aligned)
#define SIGQ    471           // SIGC / 4 float4s

// Scratch (no cudaMalloc allowed)
__device__ __align__(16) float g_part[NPATH * NCHUNK * SIGC]; // ~3.9 MB

// ---------------------------------------------------------------------------
// Chen fold body: A = A (x) B (truncated, depth 3), thread owns (i,j,kg).
// ---------------------------------------------------------------------------
__device__ __forceinline__ void chen_fold(const float* __restrict__ bp,
        int i, int j, int t144, int kg,
        float4& A3, float& A2ij, float& a1i)
{
    const float4 u4  = *(const float4*)(bp + kg * 4);                     // B1 quad
    const float  b1i = bp[i];
    const float  b1j = bp[j];
    const float4 q   = *(const float4*)(bp + L2OFF + j * 12 + kg * 4);    // B2[j] quad
    const float  b2  = bp[L2OFF + i * CCH + j];
    const float4 r   = *(const float4*)(bp + L3OFF + t144 * 12 + kg * 4); // B3 quad

    // old A1, old A2
    A3.x += r.x; A3.x = fmaf(a1i, q.x, A3.x); A3.x = fmaf(A2ij, u4.x, A3.x);
    A3.y += r.y; A3.y = fmaf(a1i, q.y, A3.y); A3.y = fmaf(A2ij, u4.y, A3.y);
    A3.z += r.z; A3.z = fmaf(a1i, q.z, A3.z); A3.z = fmaf(A2ij, u4.z, A3.z);
    A3.w += r.w; A3.w = fmaf(a1i, q.w, A3.w); A3.w = fmaf(A2ij, u4.w, A3.w);
    A2ij += b2 + a1i * b1j;   // old A1
    a1i  += b1i;
}

// ---------------------------------------------------------------------------
// Kernel 1: per-chunk partial signature.
// grid = (NCHUNK, NPATH) = 1024 blocks, block = 160 (144 active).
// Thread (i,j) owns S3[i][j][0..11] + S2[i][j] + private S1[i].
// dx in two layouts: [t][c] (broadcast float4 k-loads) and transposed [c][t].
// ---------------------------------------------------------------------------
__global__ __launch_bounds__(160) void chunk_kernel(const float* __restrict__ x,
                                                    const float* __restrict__ aug_w)
{
    __shared__ __align__(16) float dxsh[CHLEN * CCH];       // [t][c]
    __shared__ __align__(16) float dxT [CCH * TSTRIDE];     // [c][t_padded]
    __shared__ float xsh[(CHLEN + 1) * 3];
    __shared__ float awsh[8 * 3];

    const int tid   = threadIdx.x;
    const int chunk = blockIdx.x;
    const int p     = blockIdx.y;        // path id = b*2 + g
    const int b     = p >> 1;
    const int g     = p & 1;
    const int t0    = chunk * CHLEN;
    const int ns    = (chunk == NCHUNK - 1) ? (CHLEN - 1) : CHLEN;   // steps

    for (int idx = tid; idx < (ns + 1) * 3; idx += blockDim.x)
        xsh[idx] = x[(b * TT + t0) * 3 + idx];
    if (tid < 24) awsh[tid] = aug_w[g * 24 + tid];
    __syncthreads();

    for (int idx = tid; idx < ns * CCH; idx += blockDim.x) {
        int t = idx / CCH, c = idx - t * CCH;
        float xd0 = xsh[(t + 1) * 3 + 0] - xsh[t * 3 + 0];
        float xd1 = xsh[(t + 1) * 3 + 1] - xsh[t * 3 + 1];
        float xd2 = xsh[(t + 1) * 3 + 2] - xsh[t * 3 + 2];
        float v;
        if (c == 0)      v = 1.0f / 1023.0f;
        else if (c == 1) v = xd0;
        else if (c == 2) v = xd1;
        else if (c == 3) v = xd2;
        else {
            int e = c - 4;
            v = fmaf(awsh[e * 3 + 0], xd0,
                fmaf(awsh[e * 3 + 1], xd1,
                     awsh[e * 3 + 2] * xd2));
        }
        dxsh[idx] = v;
        dxT[c * TSTRIDE + t] = v;
    }
    __syncthreads();

    if (tid < 144) {
        const int i = tid / CCH, j = tid - CCH * (tid / CCH);
        float S3[12];
#pragma unroll
        for (int k = 0; k < 12; k++) S3[k] = 0.0f;
        float S2 = 0.0f;
        float s1 = 0.0f;
        const float4* __restrict__ dxq = (const float4*)dxsh;
        const float4* __restrict__ diT = (const float4*)(dxT + i * TSTRIDE);
        const float4* __restrict__ djT = (const float4*)(dxT + j * TSTRIDE);

#define SIG_STEP(tq, di_, dj_) {                                              \
        const float4 d0 = dxq[(tq) * 3 + 0];                                  \
        const float4 d1 = dxq[(tq) * 3 + 1];                                  \
        const float4 d2 = dxq[(tq) * 3 + 2];                                  \
        const float cc = fmaf(fmaf((di_), 1.0f/6.0f, 0.5f * s1), (dj_), S2);  \
        S3[0]  = fmaf(cc, d0.x, S3[0]);                                       \
        S3[1]  = fmaf(cc, d0.y, S3[1]);                                       \
        S3[2]  = fmaf(cc, d0.z, S3[2]);                                       \
        S3[3]  = fmaf(cc, d0.w, S3[3]);                                       \
        S3[4]  = fmaf(cc, d1.x, S3[4]);                                       \
        S3[5]  = fmaf(cc, d1.y, S3[5]);                                       \
        S3[6]  = fmaf(cc, d1.z, S3[6]);                                       \
        S3[7]  = fmaf(cc, d1.w, S3[7]);                                       \
        S3[8]  = fmaf(cc, d2.x, S3[8]);                                       \
        S3[9]  = fmaf(cc, d2.y, S3[9]);                                       \
        S3[10] = fmaf(cc, d2.z, S3[10]);                                      \
        S3[11] = fmaf(cc, d2.w, S3[11]);                                      \
        S2 = fmaf(fmaf((di_), 0.5f, s1), (dj_), S2);                          \
        s1 += (di_); }

        const int nq = ns >> 2;           // full quads of steps
#pragma unroll 4
        for (int tb = 0; tb < nq; tb++) {
            const float4 di4 = diT[tb];
            const float4 dj4 = djT[tb];
            SIG_STEP(tb * 4 + 0, di4.x, dj4.x);
            SIG_STEP(tb * 4 + 1, di4.y, dj4.y);
            SIG_STEP(tb * 4 + 2, di4.z, dj4.z);
            SIG_STEP(tb * 4 + 3, di4.w, dj4.w);
        }
        for (int t = nq * 4; t < ns; t++) {   // remainder (0 or 3 steps)
            const float di = dxT[i * TSTRIDE + t];
            const float dj = dxT[j * TSTRIDE + t];
            SIG_STEP(t, di, dj);
        }
#undef SIG_STEP

        float* out = &g_part[(size_t)(p * NCHUNK + chunk) * SIGC];
        if (j == 0) out[i] = s1;
        out[L2OFF + tid] = S2;
        float4* o4 = (float4*)(out + L3OFF + tid * 12);
        o4[0] = make_float4(S3[0], S3[1], S3[2],  S3[3]);
        o4[1] = make_float4(S3[4], S3[5], S3[6],  S3[7]);
        o4[2] = make_float4(S3[8], S3[9], S3[10], S3[11]);
    }
}

// ---------------------------------------------------------------------------
// Kernel 2 (fused): per-batch combine of all 16 chunk partials (both groups)
// + GEMV + sigmoid. grid = 32 (batch), block = 1024.
// Phase-pipelined staging: a phase = 4 segs x 2 groups = 60 KB bulk-staged
// into a double buffer (~4 coalesced LDG.128/thread, issued a phase ahead).
// Folds read only smem. 4 phases, 15 folds.
// ---------------------------------------------------------------------------
#define SEGS_PER_PHASE 4
#define PHASE_FLOATS   (2 * SEGS_PER_PHASE * SIGC)   // 15072
#define PHASE_QUADS    (2 * SEGS_PER_PHASE * SIGQ)   // 3768

extern __shared__ float dynbuf[];   // [2][PHASE_FLOATS]

__global__ __launch_bounds__(1024) void combine_linear_kernel(
        const float* __restrict__ lin_w,
        const float* __restrict__ lin_b,
        float* __restrict__ out)
{
    __shared__ __align__(16) float sig[2 * SIGC];   // 15 KB final signatures

    const int tid = threadIdx.x;
    const int b   = blockIdx.x;

    const float4* __restrict__ gsrc[2] = {
        (const float4*)&g_part[(size_t)(2 * b)     * NCHUNK * SIGC],
        (const float4*)&g_part[(size_t)(2 * b + 1) * NCHUNK * SIGC]
    };

    // Stage one phase (segs [4ph, 4ph+4) of both groups) into buffer par.
#define STAGE(ph, par) {                                                       \
        float* dst = dynbuf + (par) * PHASE_FLOATS;                            \
        for (int f = tid; f < PHASE_QUADS; f += 1024) {                        \
            int grp_ = f / (SEGS_PER_PHASE * SIGQ);                            \
            int rem_ = f - grp_ * (SEGS_PER_PHASE * SIGQ);                     \
            ((float4*)dst)[f] =                                                \
                gsrc[grp_][(size_t)(ph) * SEGS_PER_PHASE * SIGQ + rem_];       \
        } }

    STAGE(0, 0);
    __syncthreads();

    float4 A3 = make_float4(0.f, 0.f, 0.f, 0.f);
    float  A2ij = 0.f, a1i = 0.f;
    int grp = 0, i = 0, j = 0, t144 = 0, kg = 0;
    if (tid < 864) {
        grp  = tid / 432;
        const int u = tid - 432 * grp;
        t144 = u / 3;
        kg   = u - 3 * t144;
        i    = t144 / CCH;
        j    = t144 - CCH * i;

        const float* bp0 = dynbuf + (size_t)grp * SEGS_PER_PHASE * SIGC;
        A3   = *(const float4*)(bp0 + L3OFF + t144 * 12 + kg * 4);
        A2ij = bp0[L2OFF + t144];
        a1i  = bp0[i];
    }

    for (int ph = 0; ph < NCHUNK / SEGS_PER_PHASE; ph++) {
        const int par = ph & 1;
        if (ph + 1 < NCHUNK / SEGS_PER_PHASE) { STAGE(ph + 1, par ^ 1); }
        if (tid < 864) {
            const float* base = dynbuf + (size_t)par * PHASE_FLOATS
                                       + (size_t)grp * SEGS_PER_PHASE * SIGC;
#pragma unroll
            for (int s = 0; s < SEGS_PER_PHASE; s++) {
                if (ph == 0 && s == 0) continue;   // seg 0 used for init
                chen_fold(base + s * SIGC, i, j, t144, kg, A3, A2ij, a1i);
            }
        }
        __syncthreads();
    }
#undef STAGE

    if (tid < 864) {
        float* so = &sig[grp * SIGC];
        *(float4*)(so + L3OFF + t144 * 12 + kg * 4) = A3;
        if (kg == 0) {
            so[L2OFF + t144] = A2ij;
            if (j == 0) so[i] = a1i;
        }
    }
    __syncthreads();

    // GEMV + sigmoid: warp o -> out[b][o].
    const int o    = tid >> 5;
    const int lane = tid & 31;
    const float4* __restrict__ s4 = (const float4*)sig;
    const float4* __restrict__ w4 = (const float4*)(lin_w + (size_t)o * 2 * SIGC);
    const int NV = (2 * SIGC) / 4;   // 942

    float ax = 0.0f, ay = 0.0f, az = 0.0f, aw = 0.0f;
    for (int f = lane; f < NV; f += 32) {
        float4 sv = s4[f];
        float4 wv = w4[f];
        ax = fmaf(sv.x, wv.x, ax);
        ay = fmaf(sv.y, wv.y, ay);
        az = fmaf(sv.z, wv.z, az);
        aw = fmaf(sv.w, wv.w, aw);
    }
    float acc = (ax + ay) + (az + aw);
#pragma unroll
    for (int off = 16; off > 0; off >>= 1)
        acc += __shfl_down_sync(0xffffffffu, acc, off);
    if (lane == 0) {
        float z = acc + lin_b[o];
        out[b * 32 + o] = 1.0f / (1.0f + expf(-z));
    }
}

// ---------------------------------------------------------------------------
extern "C" void kernel_launch(void* const* d_in, const int* in_sizes, int n_in,
                              void* d_out, int out_size)
{
    const float* x     = (const float*)d_in[0];  // (32,1024,3)
    const float* aug_w = (const float*)d_in[1];  // (2,8,3)
    // d_in[2] = aug_b : unused (signature is translation-invariant)
    const float* lin_w = (const float*)d_in[3];  // (32, 3768)
    const float* lin_b = (const float*)d_in[4];  // (32,)
    float* out = (float*)d_out;                  // (32,32) float32

    const int dyn_smem = 2 * PHASE_FLOATS * (int)sizeof(float);   // 120,576 B
    cudaFuncSetAttribute(combine_linear_kernel,
                         cudaFuncAttributeMaxDynamicSharedMemorySize, dyn_smem);

    dim3 grid1(NCHUNK, NPATH);
    chunk_kernel<<<grid1, 160>>>(x, aug_w);
    combine_linear_kernel<<<32, 1024, dyn_smem>>>(lin_w, lin_b, out);
}